// round 1
// baseline (speedup 1.0000x reference)
#include <cuda_runtime.h>
#include <cuda_bf16.h>
#include <cstdint>

#define DIM_FEAT 128
#define DIM_HID  256
#define DIM_LAT  64
#define MLP_ROWS 64

#define N_MAX      200000
#define NUSER_MAX  100000

// Scratch (allocation-free rule: __device__ globals)
__device__ float g_x[(size_t)N_MAX * DIM_LAT];    // normalized concat [N,64]
__device__ float g_h[(size_t)N_MAX * DIM_LAT];    // first conv output [N,64]
__device__ float g_deg[N_MAX];                    // degree -> dis (in place)

// ---------------------------------------------------------------------------
// Fused item MLP: temp = leaky_relu(F @ W0 + b0, 0.01) @ W1 + b1
// One block per 64 rows; 256 threads. Dyn smem: A[64x128] + H[64x256] = 96KB.
// ---------------------------------------------------------------------------
__global__ void __launch_bounds__(256, 1) mlp_kernel(
    const float* __restrict__ features,
    const float* __restrict__ W0, const float* __restrict__ b0,
    const float* __restrict__ W1, const float* __restrict__ b1,
    float* __restrict__ x_out, int num_item)
{
    extern __shared__ float smem[];
    float* A_sh = smem;                      // 64*128
    float* H_sh = smem + MLP_ROWS * DIM_FEAT; // 64*256

    int row0 = blockIdx.x * MLP_ROWS;
    int t = threadIdx.x;

    // load feature tile
    for (int i = t; i < MLP_ROWS * DIM_FEAT; i += 256) {
        int r = i >> 7;           // /128
        int k = i & 127;
        int gr = row0 + r;
        A_sh[i] = (gr < num_item) ? features[(size_t)gr * DIM_FEAT + k] : 0.f;
    }
    __syncthreads();

    // layer 1: thread t owns hidden column c = t for all 64 rows
    {
        int c = t;
        float acc[MLP_ROWS];
        #pragma unroll
        for (int r = 0; r < MLP_ROWS; r++) acc[r] = 0.f;
        #pragma unroll 4
        for (int k = 0; k < DIM_FEAT; k++) {
            float w = W0[k * DIM_HID + c];
            #pragma unroll
            for (int r = 0; r < MLP_ROWS; r++) acc[r] += A_sh[r * DIM_FEAT + k] * w;
        }
        float bias = b0[c];
        #pragma unroll
        for (int r = 0; r < MLP_ROWS; r++) {
            float v = acc[r] + bias;
            H_sh[r * DIM_HID + c] = (v > 0.f) ? v : 0.01f * v;
        }
    }
    __syncthreads();

    // layer 2: thread t -> column c2 = t%64, row block rb = t/64 (16 rows each)
    {
        int c2 = t & 63;
        int rb = t >> 6;
        float acc2[16];
        #pragma unroll
        for (int r = 0; r < 16; r++) acc2[r] = 0.f;
        #pragma unroll 4
        for (int k = 0; k < DIM_HID; k++) {
            float w = W1[k * DIM_LAT + c2];
            #pragma unroll
            for (int r = 0; r < 16; r++)
                acc2[r] += H_sh[(rb * 16 + r) * DIM_HID + k] * w;
        }
        float bias = b1[c2];
        #pragma unroll
        for (int r = 0; r < 16; r++) {
            int gr = row0 + rb * 16 + r;
            if (gr < num_item) x_out[(size_t)gr * DIM_LAT + c2] = acc2[r] + bias;
        }
    }
}

// ---------------------------------------------------------------------------
// Build x = normalize(concat(preference, temp)): one warp per row.
// Item rows already sit in g_x (written by mlp_kernel); user rows read pref.
// ---------------------------------------------------------------------------
__global__ void concat_norm_kernel(const float* __restrict__ pref,
                                   float* __restrict__ x,
                                   int N, int num_user)
{
    int warp = (blockIdx.x * blockDim.x + threadIdx.x) >> 5;
    int lane = threadIdx.x & 31;
    int nwarps = (gridDim.x * blockDim.x) >> 5;
    for (int row = warp; row < N; row += nwarps) {
        const float* src = (row < num_user) ? (pref + (size_t)row * DIM_LAT)
                                            : (x + (size_t)row * DIM_LAT);
        float2 v = reinterpret_cast<const float2*>(src)[lane];
        float ss = v.x * v.x + v.y * v.y;
        #pragma unroll
        for (int o = 16; o > 0; o >>= 1) ss += __shfl_xor_sync(0xffffffffu, ss, o);
        float nrm = fmaxf(sqrtf(ss), 1e-12f);
        float s = 1.0f / nrm;
        float2 o2 = make_float2(v.x * s, v.y * s);
        reinterpret_cast<float2*>(x + (size_t)row * DIM_LAT)[lane] = o2;
    }
}

// deg[rows[e]] += 1
__global__ void deg_kernel(const int* __restrict__ rows, float* __restrict__ deg, int E)
{
    int i = blockIdx.x * blockDim.x + threadIdx.x;
    if (i < E) atomicAdd(&deg[rows[i]], 1.0f);
}

// in-place deg -> deg^-0.5
__global__ void dis_kernel(float* __restrict__ deg, int N)
{
    int i = blockIdx.x * blockDim.x + threadIdx.x;
    if (i < N) deg[i] = rsqrtf(deg[i]);
}

// ---------------------------------------------------------------------------
// GCN scatter: dst[col] += dis[row]*dis[col] * src[row].  16 threads/edge,
// float4 load + red.global.add.v4.f32 (sm_90+ vector reduction).
// ---------------------------------------------------------------------------
__global__ void conv_kernel(const int* __restrict__ rows, const int* __restrict__ cols,
                            const float* __restrict__ dis,
                            const float* __restrict__ src, float* __restrict__ dst,
                            int E)
{
    int gid = blockIdx.x * blockDim.x + threadIdx.x;
    int e = gid >> 4;
    if (e >= E) return;
    int lane = threadIdx.x & 31;
    int j = lane & 15;
    int srcLane = lane & 16;       // 0 or 16

    int r = 0, c = 0; float s = 0.f;
    if (j == 0) {
        r = rows[e];
        c = cols[e];
        s = dis[r] * dis[c];
    }
    r = __shfl_sync(0xffffffffu, r, srcLane);
    c = __shfl_sync(0xffffffffu, c, srcLane);
    s = __shfl_sync(0xffffffffu, s, srcLane);

    float4 v = *reinterpret_cast<const float4*>(src + (size_t)r * DIM_LAT + j * 4);
    float* p = dst + (size_t)c * DIM_LAT + j * 4;
    asm volatile("red.global.add.v4.f32 [%0], {%1,%2,%3,%4};"
                 :: "l"(p), "f"(v.x * s), "f"(v.y * s), "f"(v.z * s), "f"(v.w * s)
                 : "memory");
}

// out[i] = x[i] + h[i]  (seed for x_hat before conv2 scatters h1 into it)
__global__ void seed_kernel(const float* __restrict__ x, const float* __restrict__ h,
                            float* __restrict__ out, int n4)
{
    int i = blockIdx.x * blockDim.x + threadIdx.x;
    if (i < n4) {
        float4 a = reinterpret_cast<const float4*>(x)[i];
        float4 b = reinterpret_cast<const float4*>(h)[i];
        reinterpret_cast<float4*>(out)[i] =
            make_float4(a.x + b.x, a.y + b.y, a.z + b.z, a.w + b.w);
    }
}

extern "C" void kernel_launch(void* const* d_in, const int* in_sizes, int n_in,
                              void* d_out, int out_size)
{
    const int*   edge     = (const int*)d_in[0];
    const float* features = (const float*)d_in[1];
    const float* pref     = (const float*)d_in[2];
    const float* W0       = (const float*)d_in[3];
    const float* b0       = (const float*)d_in[4];
    const float* W1       = (const float*)d_in[5];
    const float* b1       = (const float*)d_in[6];

    int E        = in_sizes[0] / 2;
    int num_item = in_sizes[1] / DIM_FEAT;
    int num_user = in_sizes[2] / DIM_LAT;
    int N        = num_user + num_item;

    const int* rows = edge;
    const int* cols = edge + E;
    float* out = (float*)d_out;

    float *g_x_p, *g_h_p, *g_deg_p;
    cudaGetSymbolAddress((void**)&g_x_p,   g_x);
    cudaGetSymbolAddress((void**)&g_h_p,   g_h);
    cudaGetSymbolAddress((void**)&g_deg_p, g_deg);

    cudaFuncSetAttribute(mlp_kernel, cudaFuncAttributeMaxDynamicSharedMemorySize, 98304);

    // 1) item MLP -> g_x[num_user:]
    mlp_kernel<<<(num_item + MLP_ROWS - 1) / MLP_ROWS, 256, 98304>>>(
        features, W0, b0, W1, b1, g_x_p + (size_t)num_user * DIM_LAT, num_item);

    // 2) concat + L2 normalize -> g_x
    concat_norm_kernel<<<1024, 256>>>(pref, g_x_p, N, num_user);

    // 3) degree -> dis (in place in g_deg)
    cudaMemsetAsync(g_deg_p, 0, (size_t)N * sizeof(float));
    deg_kernel<<<(E + 255) / 256, 256>>>(rows, g_deg_p, E);
    dis_kernel<<<(N + 255) / 256, 256>>>(g_deg_p, N);

    // 4) h = conv(x)
    cudaMemsetAsync(g_h_p, 0, (size_t)N * DIM_LAT * sizeof(float));
    long long tconv = (long long)E * 16;
    int conv_grid = (int)((tconv + 255) / 256);
    conv_kernel<<<conv_grid, 256>>>(rows, cols, g_deg_p, g_x_p, g_h_p, E);

    // 5) out = x + h ; then out += conv(h)
    int n4 = N * DIM_LAT / 4;
    seed_kernel<<<(n4 + 255) / 256, 256>>>(g_x_p, g_h_p, out, n4);
    conv_kernel<<<conv_grid, 256>>>(rows, cols, g_deg_p, g_h_p, out, E);

    // 6) tail of output tuple: raw preference
    cudaMemcpyAsync(out + (size_t)N * DIM_LAT, pref,
                    (size_t)num_user * DIM_LAT * sizeof(float),
                    cudaMemcpyDeviceToDevice);
}

// round 4
// speedup vs baseline: 1.3562x; 1.3562x over previous
#include <cuda_runtime.h>
#include <cuda_bf16.h>
#include <cstdint>

#define DIM_FEAT 128
#define DIM_HID  256
#define DIM_LAT  64

#define N_MAX      200000
#define NUSER_MAX  100000
#define E_MAX      3400000

// Scratch (allocation-free rule: __device__ globals)
__device__ float g_x[(size_t)N_MAX * DIM_LAT];        // normalized concat [N,64]
__device__ float g_h[(size_t)N_MAX * DIM_LAT];        // first conv output
__device__ float g_hid[(size_t)NUSER_MAX * DIM_HID];  // MLP hidden [100k,256]
__device__ float g_deg[N_MAX];                        // degree -> dis (in place)
__device__ float g_s[E_MAX];                          // per-edge norm scale

// ---------------------------------------------------------------------------
// 3xTF32 GEMM via mma.sync.m16n8k8 (fp32-grade accuracy on tensor pipe)
// ---------------------------------------------------------------------------
__device__ __forceinline__ void mma_tf32(float& d0, float& d1, float& d2, float& d3,
                                         uint32_t a0, uint32_t a1, uint32_t a2, uint32_t a3,
                                         uint32_t b0, uint32_t b1)
{
    asm volatile("mma.sync.aligned.m16n8k8.row.col.f32.tf32.tf32.f32 "
                 "{%0,%1,%2,%3}, {%4,%5,%6,%7}, {%8,%9}, {%0,%1,%2,%3};"
                 : "+f"(d0), "+f"(d1), "+f"(d2), "+f"(d3)
                 : "r"(a0), "r"(a1), "r"(a2), "r"(a3), "r"(b0), "r"(b1));
}

__device__ __forceinline__ void split_tf32(float f, uint32_t& hi, uint32_t& lo)
{
    uint32_t u = __float_as_uint(f) & 0xffffe000u;   // truncate to tf32 mantissa
    hi = u;
    lo = __float_as_uint(f - __uint_as_float(u));    // residual (exact in tf32)
}

// C[M,N] = act(A[M,K] @ B[K,N] + bias).  Warp tile 32x32, m16n8k8 MMAs.
template<int BM, int BN, int KC, int WGM, int WGN, bool LEAKY>
__global__ void __launch_bounds__(WGM * WGN * 32)
gemm3tf32_kernel(const float* __restrict__ A, const float* __restrict__ B,
                 const float* __restrict__ bias, float* __restrict__ C,
                 int M, int K, int N)
{
    constexpr int NTHREADS = WGM * WGN * 32;
    constexpr int SA = KC + 4;     // padded strides (bank-conflict free frag loads)
    constexpr int SB = BN + 8;
    extern __shared__ float sm[];
    float* A_sh = sm;              // BM * SA
    float* B_sh = sm + BM * SA;    // KC * SB

    int tid  = threadIdx.x;
    int wid  = tid >> 5;
    int lane = tid & 31;
    int gid  = lane >> 2;          // 0..7
    int tig  = lane & 3;           // 0..3
    int wm   = wid % WGM;
    int wn   = wid / WGM;

    int row0 = blockIdx.y * BM;
    int bn0  = blockIdx.x * BN;

    float acc[2][4][4];            // 2 m-tiles x 4 n-tiles x 4 regs (32x32 warp tile)
    #pragma unroll
    for (int i = 0; i < 2; i++)
        #pragma unroll
        for (int j = 0; j < 4; j++)
            #pragma unroll
            for (int q = 0; q < 4; q++) acc[i][j][q] = 0.f;

    for (int k0 = 0; k0 < K; k0 += KC) {
        // stage A chunk [BM x KC]
        #pragma unroll
        for (int i = tid; i < BM * KC / 4; i += NTHREADS) {
            int r  = i / (KC / 4);
            int c4 = (i % (KC / 4)) * 4;
            float4 v = make_float4(0.f, 0.f, 0.f, 0.f);
            int gr = row0 + r;
            if (gr < M) v = *reinterpret_cast<const float4*>(A + (size_t)gr * K + k0 + c4);
            float* d = &A_sh[r * SA + c4];
            d[0] = v.x; d[1] = v.y; d[2] = v.z; d[3] = v.w;
        }
        // stage B chunk [KC x BN]
        #pragma unroll
        for (int i = tid; i < KC * BN / 4; i += NTHREADS) {
            int r  = i / (BN / 4);
            int c4 = (i % (BN / 4)) * 4;
            float4 v = *reinterpret_cast<const float4*>(B + (size_t)(k0 + r) * N + bn0 + c4);
            float* d = &B_sh[r * SB + c4];
            d[0] = v.x; d[1] = v.y; d[2] = v.z; d[3] = v.w;
        }
        __syncthreads();

        #pragma unroll
        for (int ks = 0; ks < KC / 8; ks++) {
            uint32_t ah[2][4], al[2][4];
            #pragma unroll
            for (int mt = 0; mt < 2; mt++) {
                int r1 = (wm * 32 + mt * 16 + gid) * SA + ks * 8 + tig;
                int r2 = r1 + 8 * SA;
                split_tf32(A_sh[r1],     ah[mt][0], al[mt][0]);
                split_tf32(A_sh[r2],     ah[mt][1], al[mt][1]);
                split_tf32(A_sh[r1 + 4], ah[mt][2], al[mt][2]);
                split_tf32(A_sh[r2 + 4], ah[mt][3], al[mt][3]);
            }
            uint32_t bh[4][2], bl[4][2];
            #pragma unroll
            for (int nt = 0; nt < 4; nt++) {
                int col = wn * 32 + nt * 8 + gid;
                split_tf32(B_sh[(ks * 8 + tig) * SB + col],     bh[nt][0], bl[nt][0]);
                split_tf32(B_sh[(ks * 8 + tig + 4) * SB + col], bh[nt][1], bl[nt][1]);
            }
            #pragma unroll
            for (int mt = 0; mt < 2; mt++)
                #pragma unroll
                for (int nt = 0; nt < 4; nt++) {
                    float* d = acc[mt][nt];
                    mma_tf32(d[0], d[1], d[2], d[3],
                             ah[mt][0], ah[mt][1], ah[mt][2], ah[mt][3],
                             bh[nt][0], bh[nt][1]);
                    mma_tf32(d[0], d[1], d[2], d[3],
                             al[mt][0], al[mt][1], al[mt][2], al[mt][3],
                             bh[nt][0], bh[nt][1]);
                    mma_tf32(d[0], d[1], d[2], d[3],
                             ah[mt][0], ah[mt][1], ah[mt][2], ah[mt][3],
                             bl[nt][0], bl[nt][1]);
                }
        }
        __syncthreads();
    }

    // epilogue: bias (+leaky), float2 stores
    #pragma unroll
    for (int mt = 0; mt < 2; mt++) {
        int r1 = row0 + wm * 32 + mt * 16 + gid;
        int r2 = r1 + 8;
        #pragma unroll
        for (int nt = 0; nt < 4; nt++) {
            int col = bn0 + wn * 32 + nt * 8 + 2 * tig;
            float bv0 = bias[col], bv1 = bias[col + 1];
            float v0 = acc[mt][nt][0] + bv0;
            float v1 = acc[mt][nt][1] + bv1;
            float v2 = acc[mt][nt][2] + bv0;
            float v3 = acc[mt][nt][3] + bv1;
            if (LEAKY) {
                v0 = (v0 > 0.f) ? v0 : 0.01f * v0;
                v1 = (v1 > 0.f) ? v1 : 0.01f * v1;
                v2 = (v2 > 0.f) ? v2 : 0.01f * v2;
                v3 = (v3 > 0.f) ? v3 : 0.01f * v3;
            }
            if (r1 < M) *reinterpret_cast<float2*>(C + (size_t)r1 * N + col) = make_float2(v0, v1);
            if (r2 < M) *reinterpret_cast<float2*>(C + (size_t)r2 * N + col) = make_float2(v2, v3);
        }
    }
}

// ---------------------------------------------------------------------------
// Degree / normalization helpers
// ---------------------------------------------------------------------------
__global__ void deg_kernel(const int* __restrict__ rows, float* __restrict__ deg, int E)
{
    int i = blockIdx.x * blockDim.x + threadIdx.x;
    if (i < E) atomicAdd(&deg[rows[i]], 1.0f);
}

__global__ void dis_kernel(float* __restrict__ deg, int N)
{
    int i = blockIdx.x * blockDim.x + threadIdx.x;
    if (i < N) deg[i] = rsqrtf(deg[i]);
}

// s[e] = dis[rows[e]] * dis[cols[e]]  (gather once, both convs reuse)
__global__ void pack_kernel(const int* __restrict__ rows, const int* __restrict__ cols,
                            const float* __restrict__ dis, float* __restrict__ s, int E)
{
    int i = blockIdx.x * blockDim.x + threadIdx.x;
    if (i < E) s[i] = dis[rows[i]] * dis[cols[i]];
}

// x = normalize(concat(preference, temp)) : one warp per row
__global__ void concat_norm_kernel(const float* __restrict__ pref,
                                   float* __restrict__ x,
                                   int N, int num_user)
{
    int warp = (blockIdx.x * blockDim.x + threadIdx.x) >> 5;
    int lane = threadIdx.x & 31;
    int nwarps = (gridDim.x * blockDim.x) >> 5;
    for (int row = warp; row < N; row += nwarps) {
        const float* src = (row < num_user) ? (pref + (size_t)row * DIM_LAT)
                                            : (x + (size_t)row * DIM_LAT);
        float2 v = reinterpret_cast<const float2*>(src)[lane];
        float ss = v.x * v.x + v.y * v.y;
        #pragma unroll
        for (int o = 16; o > 0; o >>= 1) ss += __shfl_xor_sync(0xffffffffu, ss, o);
        float sc = 1.0f / fmaxf(sqrtf(ss), 1e-12f);
        reinterpret_cast<float2*>(x + (size_t)row * DIM_LAT)[lane] =
            make_float2(v.x * sc, v.y * sc);
    }
}

// ---------------------------------------------------------------------------
// GCN scatter: dst[col] += s * src[row].  8 threads/edge, 2x red.v4 each.
// Metadata via broadcast loads (no shuffles).
// ---------------------------------------------------------------------------
__global__ void conv_kernel(const int* __restrict__ rows, const int* __restrict__ cols,
                            const float* __restrict__ s,
                            const float* __restrict__ src, float* __restrict__ dst,
                            int E)
{
    long long gid = (long long)blockIdx.x * blockDim.x + threadIdx.x;
    int e = (int)(gid >> 3);
    if (e >= E) return;
    int j = (int)gid & 7;

    int   r  = __ldg(rows + e);
    int   c  = __ldg(cols + e);
    float sc = __ldg(s + e);

    const float4* sp = reinterpret_cast<const float4*>(src + (size_t)r * DIM_LAT) + j * 2;
    float4 v0 = sp[0];
    float4 v1 = sp[1];
    float* p = dst + (size_t)c * DIM_LAT + j * 8;
    asm volatile("red.global.add.v4.f32 [%0], {%1,%2,%3,%4};"
                 :: "l"(p), "f"(v0.x * sc), "f"(v0.y * sc), "f"(v0.z * sc), "f"(v0.w * sc)
                 : "memory");
    asm volatile("red.global.add.v4.f32 [%0], {%1,%2,%3,%4};"
                 :: "l"(p + 4), "f"(v1.x * sc), "f"(v1.y * sc), "f"(v1.z * sc), "f"(v1.w * sc)
                 : "memory");
}

// out[i] = x[i] + h[i]
__global__ void seed_kernel(const float* __restrict__ x, const float* __restrict__ h,
                            float* __restrict__ out, int n4)
{
    int i = blockIdx.x * blockDim.x + threadIdx.x;
    if (i < n4) {
        float4 a = reinterpret_cast<const float4*>(x)[i];
        float4 b = reinterpret_cast<const float4*>(h)[i];
        reinterpret_cast<float4*>(out)[i] =
            make_float4(a.x + b.x, a.y + b.y, a.z + b.z, a.w + b.w);
    }
}

extern "C" void kernel_launch(void* const* d_in, const int* in_sizes, int n_in,
                              void* d_out, int out_size)
{
    const int*   edge     = (const int*)d_in[0];
    const float* features = (const float*)d_in[1];
    const float* pref     = (const float*)d_in[2];
    const float* W0       = (const float*)d_in[3];
    const float* b0       = (const float*)d_in[4];
    const float* W1       = (const float*)d_in[5];
    const float* b1       = (const float*)d_in[6];

    int E        = in_sizes[0] / 2;
    int num_item = in_sizes[1] / DIM_FEAT;
    int num_user = in_sizes[2] / DIM_LAT;
    int N        = num_user + num_item;

    const int* rows = edge;
    const int* cols = edge + E;
    float* out = (float*)d_out;

    float *g_x_p, *g_h_p, *g_hid_p, *g_deg_p, *g_s_p;
    cudaGetSymbolAddress((void**)&g_x_p,   g_x);
    cudaGetSymbolAddress((void**)&g_h_p,   g_h);
    cudaGetSymbolAddress((void**)&g_hid_p, g_hid);
    cudaGetSymbolAddress((void**)&g_deg_p, g_deg);
    cudaGetSymbolAddress((void**)&g_s_p,   g_s);

    // smem sizes
    const int smem1 = (64 * (64 + 4) + 64 * (128 + 8)) * 4;  // 52224
    const int smem2 = (64 * (64 + 4) + 64 * (64 + 8)) * 4;   // 35840
    cudaFuncSetAttribute(gemm3tf32_kernel<64, 128, 64, 2, 4, true>,
                         cudaFuncAttributeMaxDynamicSharedMemorySize, smem1);

    // degree -> dis -> per-edge scale
    cudaMemsetAsync(g_deg_p, 0, (size_t)N * sizeof(float));
    deg_kernel<<<(E + 255) / 256, 256>>>(rows, g_deg_p, E);
    dis_kernel<<<(N + 255) / 256, 256>>>(g_deg_p, N);
    pack_kernel<<<(E + 255) / 256, 256>>>(rows, cols, g_deg_p, g_s_p, E);

    // item MLP on tensor pipe (3xTF32)
    gemm3tf32_kernel<64, 128, 64, 2, 4, true>
        <<<dim3(2, (num_item + 63) / 64), 256, smem1>>>(
            features, W0, b0, g_hid_p, num_item, DIM_FEAT, DIM_HID);
    gemm3tf32_kernel<64, 64, 64, 2, 2, false>
        <<<dim3(1, (num_item + 63) / 64), 128, smem2>>>(
            g_hid_p, W1, b1, g_x_p + (size_t)num_user * DIM_LAT, num_item, DIM_HID, DIM_LAT);

    // concat + L2 normalize
    concat_norm_kernel<<<1024, 256>>>(pref, g_x_p, N, num_user);

    // h = conv(x)
    cudaMemsetAsync(g_h_p, 0, (size_t)N * DIM_LAT * sizeof(float));
    long long tconv = (long long)E * 8;
    int conv_grid = (int)((tconv + 255) / 256);
    conv_kernel<<<conv_grid, 256>>>(rows, cols, g_s_p, g_x_p, g_h_p, E);

    // out = x + h ; out += conv(h)
    int n4 = N * DIM_LAT / 4;
    seed_kernel<<<(n4 + 255) / 256, 256>>>(g_x_p, g_h_p, out, n4);
    conv_kernel<<<conv_grid, 256>>>(rows, cols, g_s_p, g_h_p, out, E);

    // output tuple tail: raw preference
    cudaMemcpyAsync(out + (size_t)N * DIM_LAT, pref,
                    (size_t)num_user * DIM_LAT * sizeof(float),
                    cudaMemcpyDeviceToDevice);
}

// round 6
// speedup vs baseline: 2.1800x; 1.6074x over previous
#include <cuda_runtime.h>
#include <cuda_bf16.h>
#include <cstdint>

#define DIM_FEAT 128
#define DIM_HID  256
#define DIM_LAT  64

#define N_MAX      200000
#define NUSER_MAX  100000
#define E_MAX      3400000
#define SCAN_BLK   1024
#define NB_MAX     ((N_MAX + SCAN_BLK - 1) / SCAN_BLK)   // 196

// Scratch (allocation-free rule: __device__ globals)
__device__ float g_x[(size_t)N_MAX * DIM_LAT];        // normalized concat [N,64]
__device__ float g_h[(size_t)N_MAX * DIM_LAT];        // first conv output
__device__ float g_hid[(size_t)NUSER_MAX * DIM_HID];  // MLP hidden
__device__ float g_deg[N_MAX];                        // out-degree -> dis (in place)
__device__ int   g_cnt[N_MAX];                        // in-degree (by col)
__device__ int   g_ptr[N_MAX + 1];                    // CSR offsets
__device__ int   g_cur[N_MAX];                        // scatter cursors
__device__ int   g_bsum[256];                         // scan block sums
__device__ int2  g_pairs[E_MAX];                      // CSR payload (row, scale)

// ---------------------------------------------------------------------------
// 3xTF32 GEMM via mma.sync.m16n8k8 (fp32-grade accuracy on tensor pipe)
// ---------------------------------------------------------------------------
__device__ __forceinline__ void mma_tf32(float& d0, float& d1, float& d2, float& d3,
                                         uint32_t a0, uint32_t a1, uint32_t a2, uint32_t a3,
                                         uint32_t b0, uint32_t b1)
{
    asm volatile("mma.sync.aligned.m16n8k8.row.col.f32.tf32.tf32.f32 "
                 "{%0,%1,%2,%3}, {%4,%5,%6,%7}, {%8,%9}, {%0,%1,%2,%3};"
                 : "+f"(d0), "+f"(d1), "+f"(d2), "+f"(d3)
                 : "r"(a0), "r"(a1), "r"(a2), "r"(a3), "r"(b0), "r"(b1));
}

__device__ __forceinline__ void split_tf32(float f, uint32_t& hi, uint32_t& lo)
{
    uint32_t u = __float_as_uint(f) & 0xffffe000u;
    hi = u;
    lo = __float_as_uint(f - __uint_as_float(u));
}

template<int BM, int BN, int KC, int WGM, int WGN, bool LEAKY>
__global__ void __launch_bounds__(WGM * WGN * 32)
gemm3tf32_kernel(const float* __restrict__ A, const float* __restrict__ B,
                 const float* __restrict__ bias, float* __restrict__ C,
                 int M, int K, int N)
{
    constexpr int NTHREADS = WGM * WGN * 32;
    constexpr int SA = KC + 4;
    constexpr int SB = BN + 8;
    extern __shared__ float sm[];
    float* A_sh = sm;
    float* B_sh = sm + BM * SA;

    int tid  = threadIdx.x;
    int wid  = tid >> 5;
    int lane = tid & 31;
    int gid  = lane >> 2;
    int tig  = lane & 3;
    int wm   = wid % WGM;
    int wn   = wid / WGM;

    int row0 = blockIdx.y * BM;
    int bn0  = blockIdx.x * BN;

    float acc[2][4][4];
    #pragma unroll
    for (int i = 0; i < 2; i++)
        #pragma unroll
        for (int j = 0; j < 4; j++)
            #pragma unroll
            for (int q = 0; q < 4; q++) acc[i][j][q] = 0.f;

    for (int k0 = 0; k0 < K; k0 += KC) {
        #pragma unroll
        for (int i = tid; i < BM * KC / 4; i += NTHREADS) {
            int r  = i / (KC / 4);
            int c4 = (i % (KC / 4)) * 4;
            float4 v = make_float4(0.f, 0.f, 0.f, 0.f);
            int gr = row0 + r;
            if (gr < M) v = *reinterpret_cast<const float4*>(A + (size_t)gr * K + k0 + c4);
            float* d = &A_sh[r * SA + c4];
            d[0] = v.x; d[1] = v.y; d[2] = v.z; d[3] = v.w;
        }
        #pragma unroll
        for (int i = tid; i < KC * BN / 4; i += NTHREADS) {
            int r  = i / (BN / 4);
            int c4 = (i % (BN / 4)) * 4;
            float4 v = *reinterpret_cast<const float4*>(B + (size_t)(k0 + r) * N + bn0 + c4);
            float* d = &B_sh[r * SB + c4];
            d[0] = v.x; d[1] = v.y; d[2] = v.z; d[3] = v.w;
        }
        __syncthreads();

        #pragma unroll
        for (int ks = 0; ks < KC / 8; ks++) {
            uint32_t ah[2][4], al[2][4];
            #pragma unroll
            for (int mt = 0; mt < 2; mt++) {
                int r1 = (wm * 32 + mt * 16 + gid) * SA + ks * 8 + tig;
                int r2 = r1 + 8 * SA;
                split_tf32(A_sh[r1],     ah[mt][0], al[mt][0]);
                split_tf32(A_sh[r2],     ah[mt][1], al[mt][1]);
                split_tf32(A_sh[r1 + 4], ah[mt][2], al[mt][2]);
                split_tf32(A_sh[r2 + 4], ah[mt][3], al[mt][3]);
            }
            uint32_t bh[4][2], bl[4][2];
            #pragma unroll
            for (int nt = 0; nt < 4; nt++) {
                int col = wn * 32 + nt * 8 + gid;
                split_tf32(B_sh[(ks * 8 + tig) * SB + col],     bh[nt][0], bl[nt][0]);
                split_tf32(B_sh[(ks * 8 + tig + 4) * SB + col], bh[nt][1], bl[nt][1]);
            }
            #pragma unroll
            for (int mt = 0; mt < 2; mt++)
                #pragma unroll
                for (int nt = 0; nt < 4; nt++) {
                    float* d = acc[mt][nt];
                    mma_tf32(d[0], d[1], d[2], d[3],
                             ah[mt][0], ah[mt][1], ah[mt][2], ah[mt][3],
                             bh[nt][0], bh[nt][1]);
                    mma_tf32(d[0], d[1], d[2], d[3],
                             al[mt][0], al[mt][1], al[mt][2], al[mt][3],
                             bh[nt][0], bh[nt][1]);
                    mma_tf32(d[0], d[1], d[2], d[3],
                             ah[mt][0], ah[mt][1], ah[mt][2], ah[mt][3],
                             bl[nt][0], bl[nt][1]);
                }
        }
        __syncthreads();
    }

    #pragma unroll
    for (int mt = 0; mt < 2; mt++) {
        int r1 = row0 + wm * 32 + mt * 16 + gid;
        int r2 = r1 + 8;
        #pragma unroll
        for (int nt = 0; nt < 4; nt++) {
            int col = bn0 + wn * 32 + nt * 8 + 2 * tig;
            float bv0 = bias[col], bv1 = bias[col + 1];
            float v0 = acc[mt][nt][0] + bv0;
            float v1 = acc[mt][nt][1] + bv1;
            float v2 = acc[mt][nt][2] + bv0;
            float v3 = acc[mt][nt][3] + bv1;
            if (LEAKY) {
                v0 = (v0 > 0.f) ? v0 : 0.01f * v0;
                v1 = (v1 > 0.f) ? v1 : 0.01f * v1;
                v2 = (v2 > 0.f) ? v2 : 0.01f * v2;
                v3 = (v3 > 0.f) ? v3 : 0.01f * v3;
            }
            if (r1 < M) *reinterpret_cast<float2*>(C + (size_t)r1 * N + col) = make_float2(v0, v1);
            if (r2 < M) *reinterpret_cast<float2*>(C + (size_t)r2 * N + col) = make_float2(v2, v3);
        }
    }
}

// ---------------------------------------------------------------------------
// CSR build: count (out-deg + in-deg), scan, scatter (row, s) pairs by col
// ---------------------------------------------------------------------------
__global__ void degcnt_kernel(const int* __restrict__ rows, const int* __restrict__ cols,
                              float* __restrict__ deg, int* __restrict__ cnt, int E)
{
    int i = blockIdx.x * blockDim.x + threadIdx.x;
    if (i < E) {
        atomicAdd(&deg[rows[i]], 1.0f);
        atomicAdd(&cnt[cols[i]], 1);
    }
}

__global__ void dis_kernel(float* __restrict__ deg, int N)
{
    int i = blockIdx.x * blockDim.x + threadIdx.x;
    if (i < N) deg[i] = rsqrtf(deg[i]);
}

// exclusive scan within 1024-elem blocks + per-block totals
__global__ void __launch_bounds__(SCAN_BLK)
scan_block_kernel(const int* __restrict__ cnt, int* __restrict__ out,
                  int* __restrict__ bsum, int N)
{
    __shared__ int ws[32];
    int tid = threadIdx.x;
    int gid = blockIdx.x * SCAN_BLK + tid;
    int v = (gid < N) ? cnt[gid] : 0;
    int lane = tid & 31, wid = tid >> 5;
    int x = v;
    #pragma unroll
    for (int o = 1; o < 32; o <<= 1) {
        int y = __shfl_up_sync(0xffffffffu, x, o);
        if (lane >= o) x += y;
    }
    if (lane == 31) ws[wid] = x;
    __syncthreads();
    if (wid == 0) {
        int s = ws[lane];
        #pragma unroll
        for (int o = 1; o < 32; o <<= 1) {
            int y = __shfl_up_sync(0xffffffffu, s, o);
            if (lane >= o) s += y;
        }
        ws[lane] = s;
    }
    __syncthreads();
    int incl = x + ((wid > 0) ? ws[wid - 1] : 0);
    if (gid < N) out[gid] = incl - v;     // exclusive within block
    if (tid == SCAN_BLK - 1) bsum[blockIdx.x] = incl;
}

// exclusive scan of block sums (nb <= 256), single block of 256
__global__ void scan_sums_kernel(int* __restrict__ bs, int nb)
{
    __shared__ int ws[8];
    int tid = threadIdx.x;
    int v = (tid < nb) ? bs[tid] : 0;
    int lane = tid & 31, wid = tid >> 5;
    int x = v;
    #pragma unroll
    for (int o = 1; o < 32; o <<= 1) {
        int y = __shfl_up_sync(0xffffffffu, x, o);
        if (lane >= o) x += y;
    }
    if (lane == 31) ws[wid] = x;
    __syncthreads();
    if (tid == 0) {
        int acc = 0;
        #pragma unroll
        for (int i = 0; i < 8; i++) { int t = ws[i]; ws[i] = acc; acc += t; }
    }
    __syncthreads();
    if (tid < nb) bs[tid] = x - v + ws[wid];
}

// add block offsets; init cursors; set ptr[N]=E
__global__ void __launch_bounds__(SCAN_BLK)
scan_add_kernel(int* __restrict__ ptr, const int* __restrict__ bs,
                int* __restrict__ cur, int N, int E)
{
    int gid = blockIdx.x * SCAN_BLK + threadIdx.x;
    if (gid < N) {
        int p = ptr[gid] + bs[blockIdx.x];
        ptr[gid] = p;
        cur[gid] = p;
    }
    if (gid == 0) ptr[N] = E;
}

__global__ void scatter_kernel(const int* __restrict__ rows, const int* __restrict__ cols,
                               const float* __restrict__ dis,
                               int* __restrict__ cur, int2* __restrict__ pairs, int E)
{
    int i = blockIdx.x * blockDim.x + threadIdx.x;
    if (i < E) {
        int r = rows[i], c = cols[i];
        float s = dis[r] * dis[c];
        int pos = atomicAdd(&cur[c], 1);
        pairs[pos] = make_int2(r, __float_as_int(s));
    }
}

// ---------------------------------------------------------------------------
// x = normalize(concat(preference, temp)) : one warp per row
// ---------------------------------------------------------------------------
__global__ void concat_norm_kernel(const float* __restrict__ pref,
                                   float* __restrict__ x,
                                   int N, int num_user)
{
    int warp = (blockIdx.x * blockDim.x + threadIdx.x) >> 5;
    int lane = threadIdx.x & 31;
    int nwarps = (gridDim.x * blockDim.x) >> 5;
    for (int row = warp; row < N; row += nwarps) {
        const float* src = (row < num_user) ? (pref + (size_t)row * DIM_LAT)
                                            : (x + (size_t)row * DIM_LAT);
        float2 v = reinterpret_cast<const float2*>(src)[lane];
        float ss = v.x * v.x + v.y * v.y;
        #pragma unroll
        for (int o = 16; o > 0; o >>= 1) ss += __shfl_xor_sync(0xffffffffu, ss, o);
        float sc = 1.0f / fmaxf(sqrtf(ss), 1e-12f);
        reinterpret_cast<float2*>(x + (size_t)row * DIM_LAT)[lane] =
            make_float2(v.x * sc, v.y * sc);
    }
}

// ---------------------------------------------------------------------------
// Pull conv: one warp per dst node, lane owns float2. No atomics.
// FUSE: accumulator seeded with x0[d]+h0[d] (for x_hat = x + h + conv(h))
// ---------------------------------------------------------------------------
template<bool FUSE>
__global__ void __launch_bounds__(256)
conv_pull_kernel(const int2* __restrict__ pairs, const int* __restrict__ ptr,
                 const float* __restrict__ src,
                 const float* __restrict__ x0, const float* __restrict__ h0,
                 float* __restrict__ dst, int N)
{
    int warp = (blockIdx.x * blockDim.x + threadIdx.x) >> 5;
    if (warp >= N) return;
    int lane = threadIdx.x & 31;
    int beg = __ldg(ptr + warp);
    int end = __ldg(ptr + warp + 1);

    float2 acc = make_float2(0.f, 0.f);
    if (FUSE) {
        float2 a = reinterpret_cast<const float2*>(x0 + (size_t)warp * DIM_LAT)[lane];
        float2 b = reinterpret_cast<const float2*>(h0 + (size_t)warp * DIM_LAT)[lane];
        acc.x = a.x + b.x;
        acc.y = a.y + b.y;
    }

    int i = beg;
    // unroll-by-2 to expose MLP on the gather chain
    for (; i + 2 <= end; i += 2) {
        int2 p0 = __ldg(pairs + i);
        int2 p1 = __ldg(pairs + i + 1);
        float2 v0 = __ldg(reinterpret_cast<const float2*>(src + (size_t)p0.x * DIM_LAT) + lane);
        float2 v1 = __ldg(reinterpret_cast<const float2*>(src + (size_t)p1.x * DIM_LAT) + lane);
        float s0 = __int_as_float(p0.y);
        float s1 = __int_as_float(p1.y);
        acc.x += s0 * v0.x + s1 * v1.x;
        acc.y += s0 * v0.y + s1 * v1.y;
    }
    if (i < end) {
        int2 p0 = __ldg(pairs + i);
        float2 v0 = __ldg(reinterpret_cast<const float2*>(src + (size_t)p0.x * DIM_LAT) + lane);
        float s0 = __int_as_float(p0.y);
        acc.x += s0 * v0.x;
        acc.y += s0 * v0.y;
    }
    reinterpret_cast<float2*>(dst + (size_t)warp * DIM_LAT)[lane] = acc;
}

extern "C" void kernel_launch(void* const* d_in, const int* in_sizes, int n_in,
                              void* d_out, int out_size)
{
    const int*   edge     = (const int*)d_in[0];
    const float* features = (const float*)d_in[1];
    const float* pref     = (const float*)d_in[2];
    const float* W0       = (const float*)d_in[3];
    const float* b0       = (const float*)d_in[4];
    const float* W1       = (const float*)d_in[5];
    const float* b1       = (const float*)d_in[6];

    int E        = in_sizes[0] / 2;
    int num_item = in_sizes[1] / DIM_FEAT;
    int num_user = in_sizes[2] / DIM_LAT;
    int N        = num_user + num_item;

    const int* rows = edge;
    const int* cols = edge + E;
    float* out = (float*)d_out;

    float *g_x_p, *g_h_p, *g_hid_p, *g_deg_p;
    int *g_cnt_p, *g_ptr_p, *g_cur_p, *g_bsum_p;
    int2 *g_pairs_p;
    cudaGetSymbolAddress((void**)&g_x_p,    g_x);
    cudaGetSymbolAddress((void**)&g_h_p,    g_h);
    cudaGetSymbolAddress((void**)&g_hid_p,  g_hid);
    cudaGetSymbolAddress((void**)&g_deg_p,  g_deg);
    cudaGetSymbolAddress((void**)&g_cnt_p,  g_cnt);
    cudaGetSymbolAddress((void**)&g_ptr_p,  g_ptr);
    cudaGetSymbolAddress((void**)&g_cur_p,  g_cur);
    cudaGetSymbolAddress((void**)&g_bsum_p, g_bsum);
    cudaGetSymbolAddress((void**)&g_pairs_p, g_pairs);

    const int smem1 = (64 * (64 + 4) + 64 * (128 + 8)) * 4;
    const int smem2 = (64 * (64 + 4) + 64 * (64 + 8)) * 4;
    cudaFuncSetAttribute(gemm3tf32_kernel<64, 128, 64, 2, 4, true>,
                         cudaFuncAttributeMaxDynamicSharedMemorySize, smem1);

    int nb = (N + SCAN_BLK - 1) / SCAN_BLK;

    // --- CSR build: counts -> dis -> scan -> scatter ---
    cudaMemsetAsync(g_deg_p, 0, (size_t)N * sizeof(float));
    cudaMemsetAsync(g_cnt_p, 0, (size_t)N * sizeof(int));
    degcnt_kernel<<<(E + 255) / 256, 256>>>(rows, cols, g_deg_p, g_cnt_p, E);
    dis_kernel<<<(N + 255) / 256, 256>>>(g_deg_p, N);
    scan_block_kernel<<<nb, SCAN_BLK>>>(g_cnt_p, g_ptr_p, g_bsum_p, N);
    scan_sums_kernel<<<1, 256>>>(g_bsum_p, nb);
    scan_add_kernel<<<nb, SCAN_BLK>>>(g_ptr_p, g_bsum_p, g_cur_p, N, E);
    scatter_kernel<<<(E + 255) / 256, 256>>>(rows, cols, g_deg_p, g_cur_p, g_pairs_p, E);

    // --- item MLP on tensor pipe (3xTF32) ---
    gemm3tf32_kernel<64, 128, 64, 2, 4, true>
        <<<dim3(2, (num_item + 63) / 64), 256, smem1>>>(
            features, W0, b0, g_hid_p, num_item, DIM_FEAT, DIM_HID);
    gemm3tf32_kernel<64, 64, 64, 2, 2, false>
        <<<dim3(1, (num_item + 63) / 64), 128, smem2>>>(
            g_hid_p, W1, b1, g_x_p + (size_t)num_user * DIM_LAT, num_item, DIM_HID, DIM_LAT);

    // --- concat + L2 normalize ---
    concat_norm_kernel<<<1024, 256>>>(pref, g_x_p, N, num_user);

    // --- h = conv(x) (pull, no atomics, no memset) ---
    int conv_blocks = (int)(((long long)N * 32 + 255) / 256);
    conv_pull_kernel<false><<<conv_blocks, 256>>>(
        g_pairs_p, g_ptr_p, g_x_p, nullptr, nullptr, g_h_p, N);

    // --- out = x + h + conv(h) (fused seed, direct to d_out) ---
    conv_pull_kernel<true><<<conv_blocks, 256>>>(
        g_pairs_p, g_ptr_p, g_h_p, g_x_p, g_h_p, out, N);

    // output tuple tail: raw preference
    cudaMemcpyAsync(out + (size_t)N * DIM_LAT, pref,
                    (size_t)num_user * DIM_LAT * sizeof(float),
                    cudaMemcpyDeviceToDevice);
}